// round 14
// baseline (speedup 1.0000x reference)
#include <cuda_runtime.h>
#include <cstdint>

// Row-wise top-k threshold mask — two-kernel phase-separated version.
//   K1: pure write stream — zero-fill all of out (unidirectional DRAM writes).
//   K2: pure read stream — read x once, compact candidates (v >= T0,
//       count-validated, fused pass-0 hist), exact radix select, scatter
//       the ~k survivors into the pre-zeroed out.
// Total DRAM traffic = 1 read + 1 write of 512 MB (the floor), but each
// kernel is a unidirectional stream, avoiding HBM read/write turnaround.
// Full-row fallback in K2 keeps arbitrary inputs correct.

constexpr int COLS    = 16384;
constexpr int THREADS = 256;
constexpr int VEC4    = COLS / THREADS / 4;   // 16 float4 per thread
constexpr int CAP     = 2048;                 // candidate buffer capacity

// Order-preserving float -> uint32 key (larger float => larger key)
__device__ __forceinline__ unsigned f2key(float f) {
    unsigned u = __float_as_uint(f);
    unsigned m = (unsigned)((int)u >> 31) | 0x80000000u;
    return u ^ m;
}
__device__ __forceinline__ float key2f(unsigned k) {
    unsigned u = (k & 0x80000000u) ? (k & 0x7FFFFFFFu) : ~k;
    return __uint_as_float(u);
}

// ---------- K1: pure streaming zero-fill ----------
__global__ __launch_bounds__(THREADS, 8)
void zerofill_kernel(float4* __restrict__ out)
{
    const size_t base = (size_t)blockIdx.x * (COLS / 4);
    const float4 z4 = make_float4(0.f, 0.f, 0.f, 0.f);
    #pragma unroll
    for (int j = 0; j < VEC4; j++)
        out[base + threadIdx.x + j * THREADS] = z4;
}

// Block radix-select step over 256 bins (256 threads, one bin each).
__device__ __forceinline__ unsigned select_digit(
    int* s_hist, int* s_warp, int* s_kk, unsigned* s_digit, int tid, int lane)
{
    int h = s_hist[255 - tid];
    int v = h;
    #pragma unroll
    for (int o = 1; o < 32; o <<= 1) {
        int n = __shfl_up_sync(0xFFFFFFFFu, v, o);
        if (lane >= o) v += n;
    }
    if (lane == 31) s_warp[tid >> 5] = v;
    __syncthreads();
    if (tid < 8) {
        int ws = s_warp[tid];
        #pragma unroll
        for (int o = 1; o < 8; o <<= 1) {
            int n = __shfl_up_sync(0xFFu, ws, o);
            if (tid >= o) ws += n;
        }
        s_warp[tid] = ws;
    }
    const int kk_cur = *s_kk;
    __syncthreads();
    const int incl   = v + ((tid >= 32) ? s_warp[(tid >> 5) - 1] : 0); // count >= bucket
    const int cnt_gt = incl - h;                                       // count >  bucket
    if (cnt_gt < kk_cur && kk_cur <= incl) {
        *s_digit = (unsigned)(255 - tid);
        *s_kk    = kk_cur - cnt_gt;
    }
    __syncthreads();
    return *s_digit;
}

// ---------- K2: read + select + scatter (out already zeroed) ----------
__global__ __launch_bounds__(THREADS, 8)
void topk_select_kernel(const float* __restrict__ x,
                        float* __restrict__ out,
                        const int* __restrict__ kptr)
{
    __shared__ int                s_hist[256];
    __shared__ int                s_warp[8];
    __shared__ unsigned long long s_cand[CAP];   // (key << 32) | col
    __shared__ int                s_ncand;
    __shared__ int                s_kk;
    __shared__ unsigned           s_digit;

    const int    tid  = threadIdx.x;
    const int    lane = tid & 31;
    const size_t base = (size_t)blockIdx.x * COLS;
    const float4* xv  = reinterpret_cast<const float4*>(x + base);

    const int kk0 = (kptr != nullptr) ? kptr[0] : 64;
    if (tid == 0) { s_ncand = 0; s_kk = kk0; }
    s_hist[tid] = 0;                 // pass-0 histogram, filled during Pass A
    __syncthreads();

    // ---- Pass A: pure read stream — compact candidates + pass-0 hist ----
    // Per element: LDG(1/4) + FSETP, all independent (flat predicated form).
    // Rare branch (~2.3%): counter atomic + STS.64 + hist atomic.
    const float T0 = 2.0f;
    #pragma unroll
    for (int j = 0; j < VEC4; j++) {
        const int pos = tid + j * THREADS;
        float4 v = xv[pos];
        float vs[4] = {v.x, v.y, v.z, v.w};
        #pragma unroll
        for (int t = 0; t < 4; t++) {
            if (vs[t] >= T0) {
                const int idx = atomicAdd(&s_ncand, 1);
                if (idx < CAP) {
                    const unsigned key = f2key(vs[t]);
                    s_cand[idx] = ((unsigned long long)key << 32)
                                | (unsigned)(pos * 4 + t);
                    atomicAdd(&s_hist[key >> 24], 1);   // fused pass-0 hist
                }
            }
        }
    }
    __syncthreads();
    const int  ncand  = s_ncand;
    const bool useBuf = (ncand >= kk0 && ncand <= CAP);

    unsigned prefix = 0, prefmask = 0;

    if (useBuf) {
        // ---- Pass 0: histogram already built during Pass A ----
        const unsigned dig0 = select_digit(s_hist, s_warp, &s_kk, &s_digit, tid, lane);
        prefix   = dig0 << 24;
        prefmask = 255u << 24;
        __syncthreads();

        // ---- Passes 1..3 over the candidate buffer ----
        #pragma unroll 1
        for (int p = 1; p < 4; p++) {
            const int shift = 24 - p * 8;

            s_hist[tid] = 0;
            __syncthreads();

            const int nloop = (ncand + THREADS - 1) / THREADS * THREADS;
            for (int i = tid; i < nloop; i += THREADS) {
                const unsigned key  = (i < ncand) ? (unsigned)(s_cand[i] >> 32) : 0u;
                const bool     cand = (i < ncand) && ((key & prefmask) == prefix);
                const unsigned d    = cand ? ((key >> shift) & 255u) : 0xFFFFFFFFu;
                const unsigned m    = __match_any_sync(0xFFFFFFFFu, d);
                if (cand && lane == (__ffs(m) - 1)) atomicAdd(&s_hist[d], __popc(m));
            }
            __syncthreads();

            const unsigned dig = select_digit(s_hist, s_warp, &s_kk, &s_digit, tid, lane);
            prefix   |= dig << shift;
            prefmask |= 255u << shift;
            __syncthreads();
        }
    } else {
        // ---- Fallback: full-row 4-pass radix from gmem (arbitrary inputs) ----
        #pragma unroll 1
        for (int p = 0; p < 4; p++) {
            const int shift = 24 - p * 8;

            s_hist[tid] = 0;
            __syncthreads();

            #pragma unroll 4
            for (int j = 0; j < VEC4; j++) {
                float4 v = xv[tid + j * THREADS];
                unsigned ks[4] = {f2key(v.x), f2key(v.y), f2key(v.z), f2key(v.w)};
                #pragma unroll
                for (int t = 0; t < 4; t++) {
                    const bool     cand = ((ks[t] & prefmask) == prefix);
                    const unsigned d    = cand ? ((ks[t] >> shift) & 255u) : 0xFFFFFFFFu;
                    const unsigned m    = __match_any_sync(0xFFFFFFFFu, d);
                    if (cand && lane == (__ffs(m) - 1)) atomicAdd(&s_hist[d], __popc(m));
                }
            }
            __syncthreads();

            const unsigned dig = select_digit(s_hist, s_warp, &s_kk, &s_digit, tid, lane);
            prefix   |= dig << shift;
            prefmask |= 255u << shift;
            __syncthreads();
        }
    }

    const unsigned thresh = prefix;          // exact key of the k-th largest

    // ---- Pass B: scatter survivors only (~k per row); out pre-zeroed by K1 ----
    if (useBuf) {
        for (int i = tid; i < ncand; i += THREADS) {
            const unsigned long long kv = s_cand[i];
            const unsigned key = (unsigned)(kv >> 32);
            if (key >= thresh)
                out[base + (unsigned)(kv & 0xFFFFFFFFu)] = key2f(key);
        }
    } else {
        // fallback: conditional re-read scatter
        const float t = key2f(thresh);
        #pragma unroll 4
        for (int j = 0; j < VEC4; j++) {
            const int pos = tid + j * THREADS;
            float4 v = xv[pos];
            float vs[4] = {v.x, v.y, v.z, v.w};
            #pragma unroll
            for (int q = 0; q < 4; q++)
                if (vs[q] >= t) out[base + pos * 4 + q] = vs[q];
        }
    }
}

extern "C" void kernel_launch(void* const* d_in, const int* in_sizes, int n_in,
                              void* d_out, int out_size)
{
    const float* x  = (const float*)d_in[0];
    const int*   kp = (n_in >= 2) ? (const int*)d_in[1] : nullptr;
    float*       o  = (float*)d_out;

    const int rows = in_sizes[0] / COLS;

    // K1: unidirectional write stream (zero-fill).
    zerofill_kernel<<<rows, THREADS>>>(reinterpret_cast<float4*>(o));
    // K2: unidirectional read stream + select + tiny scatter.
    topk_select_kernel<<<rows, THREADS>>>(x, o, kp);
}

// round 15
// speedup vs baseline: 1.2081x; 1.2081x over previous
#include <cuda_runtime.h>
#include <cstdint>

// Row-wise top-k threshold mask — FINAL (R12 structure).
// out[i,j] = x[i,j] if x[i,j] >= (k-th largest of row i) else 0.
// One 256-thread CTA per row, 8 CTAs/SM (100% occ) for phase overlap.
// Single fused streaming pass: read x once, store zeros to all of out,
// compact candidates (v >= T0, count-validated) with their column indices,
// AND accumulate the pass-0 (top byte) radix histogram in the same rare
// branch. Exact radix select then needs only 3 more passes over the small
// candidate buffer; survivors are scattered at the end.
// x is NEVER re-read on the fast path -> DRAM traffic = 1 read + 1 write
// (the floor), moved at ~6.33 TB/s (the measured effective HBM ceiling:
// a pure-write kernel hits the same rate, so no turnaround penalty exists
// to recover — verified R13).
// Full-row fallback (4 passes from gmem) keeps arbitrary inputs correct.
//
// NOTE: the flat per-element predicated form of Pass A is load-bearing.
// Quad-level branches (R10) or warp-aggregation chains (R4/R5) break
// ptxas's front-batching of the 16 LDG.128s and cost ~12% DRAM throughput.
// Phase-separating the read and write streams (R13) loses the select-phase
// overlap and is ~20% slower.

constexpr int COLS    = 16384;
constexpr int THREADS = 256;
constexpr int VEC4    = COLS / THREADS / 4;   // 16 float4 per thread
constexpr int CAP     = 2048;                 // candidate buffer capacity

// Order-preserving float -> uint32 key (larger float => larger key)
__device__ __forceinline__ unsigned f2key(float f) {
    unsigned u = __float_as_uint(f);
    unsigned m = (unsigned)((int)u >> 31) | 0x80000000u;
    return u ^ m;
}
__device__ __forceinline__ float key2f(unsigned k) {
    unsigned u = (k & 0x80000000u) ? (k & 0x7FFFFFFFu) : ~k;
    return __uint_as_float(u);
}

// Block radix-select step over 256 bins (256 threads, one bin each).
// Picks bucket containing the *s_kk-th largest, updates *s_kk, returns digit.
__device__ __forceinline__ unsigned select_digit(
    int* s_hist, int* s_warp, int* s_kk, unsigned* s_digit, int tid, int lane)
{
    int h = s_hist[255 - tid];
    int v = h;
    #pragma unroll
    for (int o = 1; o < 32; o <<= 1) {
        int n = __shfl_up_sync(0xFFFFFFFFu, v, o);
        if (lane >= o) v += n;
    }
    if (lane == 31) s_warp[tid >> 5] = v;
    __syncthreads();
    if (tid < 8) {
        int ws = s_warp[tid];
        #pragma unroll
        for (int o = 1; o < 8; o <<= 1) {
            int n = __shfl_up_sync(0xFFu, ws, o);
            if (tid >= o) ws += n;
        }
        s_warp[tid] = ws;
    }
    const int kk_cur = *s_kk;
    __syncthreads();
    const int incl   = v + ((tid >= 32) ? s_warp[(tid >> 5) - 1] : 0); // count >= bucket
    const int cnt_gt = incl - h;                                       // count >  bucket
    if (cnt_gt < kk_cur && kk_cur <= incl) {
        *s_digit = (unsigned)(255 - tid);
        *s_kk    = kk_cur - cnt_gt;
    }
    __syncthreads();
    return *s_digit;
}

__global__ __launch_bounds__(THREADS, 8)
void topk_mask_kernel(const float* __restrict__ x,
                      float* __restrict__ out,
                      const int* __restrict__ kptr)
{
    __shared__ int                s_hist[256];
    __shared__ int                s_warp[8];
    __shared__ unsigned long long s_cand[CAP];   // (key << 32) | col
    __shared__ int                s_ncand;
    __shared__ int                s_kk;
    __shared__ unsigned           s_digit;

    const int    tid  = threadIdx.x;
    const int    lane = tid & 31;
    const size_t base = (size_t)blockIdx.x * COLS;
    const float4* xv  = reinterpret_cast<const float4*>(x + base);
    float4*       ov  = reinterpret_cast<float4*>(out + base);

    const int kk0 = (kptr != nullptr) ? kptr[0] : 64;
    if (tid == 0) { s_ncand = 0; s_kk = kk0; }
    s_hist[tid] = 0;                 // pass-0 histogram, filled during Pass A
    __syncthreads();

    // ---- Pass A: fused stream — read x, zero out, compact + pass-0 hist ----
    // Per element: LDG(1/4) + FSETP + STG(1/4 zeros), all independent.
    // Rare branch (~2.3%): counter atomic + STS.64 + hist atomic.
    const float  T0 = 2.0f;
    const float4 z4 = make_float4(0.f, 0.f, 0.f, 0.f);
    #pragma unroll
    for (int j = 0; j < VEC4; j++) {
        const int pos = tid + j * THREADS;
        float4 v = xv[pos];
        ov[pos] = z4;
        float vs[4] = {v.x, v.y, v.z, v.w};
        #pragma unroll
        for (int t = 0; t < 4; t++) {
            if (vs[t] >= T0) {
                const int idx = atomicAdd(&s_ncand, 1);
                if (idx < CAP) {
                    const unsigned key = f2key(vs[t]);
                    s_cand[idx] = ((unsigned long long)key << 32)
                                | (unsigned)(pos * 4 + t);
                    atomicAdd(&s_hist[key >> 24], 1);   // fused pass-0 hist
                }
            }
        }
    }
    __syncthreads();
    const int  ncand  = s_ncand;
    const bool useBuf = (ncand >= kk0 && ncand <= CAP);

    unsigned prefix = 0, prefmask = 0;

    if (useBuf) {
        // ---- Pass 0: histogram already built during Pass A ----
        const unsigned dig0 = select_digit(s_hist, s_warp, &s_kk, &s_digit, tid, lane);
        prefix   = dig0 << 24;
        prefmask = 255u << 24;
        __syncthreads();

        // ---- Passes 1..3 over the candidate buffer ----
        #pragma unroll 1
        for (int p = 1; p < 4; p++) {
            const int shift = 24 - p * 8;

            s_hist[tid] = 0;
            __syncthreads();

            const int nloop = (ncand + THREADS - 1) / THREADS * THREADS;
            for (int i = tid; i < nloop; i += THREADS) {
                const unsigned key  = (i < ncand) ? (unsigned)(s_cand[i] >> 32) : 0u;
                const bool     cand = (i < ncand) && ((key & prefmask) == prefix);
                const unsigned d    = cand ? ((key >> shift) & 255u) : 0xFFFFFFFFu;
                const unsigned m    = __match_any_sync(0xFFFFFFFFu, d);
                if (cand && lane == (__ffs(m) - 1)) atomicAdd(&s_hist[d], __popc(m));
            }
            __syncthreads();

            const unsigned dig = select_digit(s_hist, s_warp, &s_kk, &s_digit, tid, lane);
            prefix   |= dig << shift;
            prefmask |= 255u << shift;
            __syncthreads();
        }
    } else {
        // ---- Fallback: full-row 4-pass radix from gmem (arbitrary inputs) ----
        #pragma unroll 1
        for (int p = 0; p < 4; p++) {
            const int shift = 24 - p * 8;

            s_hist[tid] = 0;
            __syncthreads();

            #pragma unroll 4
            for (int j = 0; j < VEC4; j++) {
                float4 v = xv[tid + j * THREADS];
                unsigned ks[4] = {f2key(v.x), f2key(v.y), f2key(v.z), f2key(v.w)};
                #pragma unroll
                for (int t = 0; t < 4; t++) {
                    const bool     cand = ((ks[t] & prefmask) == prefix);
                    const unsigned d    = cand ? ((ks[t] >> shift) & 255u) : 0xFFFFFFFFu;
                    const unsigned m    = __match_any_sync(0xFFFFFFFFu, d);
                    if (cand && lane == (__ffs(m) - 1)) atomicAdd(&s_hist[d], __popc(m));
                }
            }
            __syncthreads();

            const unsigned dig = select_digit(s_hist, s_warp, &s_kk, &s_digit, tid, lane);
            prefix   |= dig << shift;
            prefmask |= 255u << shift;
            __syncthreads();
        }
    }

    const unsigned thresh = prefix;          // exact key of the k-th largest

    // ---- Pass B: scatter survivors only (~k per row) ----
    if (useBuf) {
        for (int i = tid; i < ncand; i += THREADS) {
            const unsigned long long kv = s_cand[i];
            const unsigned key = (unsigned)(kv >> 32);
            if (key >= thresh)
                out[base + (unsigned)(kv & 0xFFFFFFFFu)] = key2f(key);
        }
    } else {
        // fallback: conditional re-read scatter (out already zeroed)
        const float t = key2f(thresh);
        #pragma unroll 4
        for (int j = 0; j < VEC4; j++) {
            const int pos = tid + j * THREADS;
            float4 v = xv[pos];
            float vs[4] = {v.x, v.y, v.z, v.w};
            #pragma unroll
            for (int q = 0; q < 4; q++)
                if (vs[q] >= t) out[base + pos * 4 + q] = vs[q];
        }
    }
}

extern "C" void kernel_launch(void* const* d_in, const int* in_sizes, int n_in,
                              void* d_out, int out_size)
{
    const float* x  = (const float*)d_in[0];
    const int*   kp = (n_in >= 2) ? (const int*)d_in[1] : nullptr;
    float*       o  = (float*)d_out;

    const int rows = in_sizes[0] / COLS;
    topk_mask_kernel<<<rows, THREADS>>>(x, o, kp);
}